// round 1
// baseline (speedup 1.0000x reference)
#include <cuda_runtime.h>
#include <math.h>

// ---------------- problem dims ----------------
#define NN   128
#define TT   16
#define DD   25
#define HH   256
#define HCC  512
#define HII  128
#define EE   128
#define HPP  256
#define LL   608          // D*(D-1)+8
#define KK   8
#define RKN  2
#define DHH  (DD*HH)      // 6400
#define NDD  (NN*DD)      // 3200

// ---------------- persistent device scratch (no allocs allowed) ----------------
__device__ float g_h   [NN*DHH];      // state h (N,D,H)
__device__ float g_adj [NN*DD*DD];    // per-sample controlled adjacency
__device__ float g_t1  [NDD*HCC];     // layer-1 activations of cfn (3200 x 512)
__device__ float g_kcur[NN*DHH];      // current RK slope k_i
__device__ float g_acc [NN*DHH];      // RK accumulator k1+2k2+2k3(+k4)

__device__ __forceinline__ float get_dt(const float* __restrict__ et,
                                        const float* __restrict__ t0,
                                        int n, int t) {
    float tp = (t == 0) ? t0[n] : et[n*TT + t - 1];
    return et[n*TT + t] - tp;
}

// ---------------- block reductions (256 threads) ----------------
__device__ __forceinline__ float blk_max256(float v, float* red, int tid) {
    red[tid] = v; __syncthreads();
    #pragma unroll
    for (int s = 128; s > 0; s >>= 1) {
        if (tid < s) red[tid] = fmaxf(red[tid], red[tid + s]);
        __syncthreads();
    }
    v = red[0]; __syncthreads();
    return v;
}
__device__ __forceinline__ float blk_sum256(float v, float* red, int tid) {
    red[tid] = v; __syncthreads();
    #pragma unroll
    for (int s = 128; s > 0; s >>= 1) {
        if (tid < s) red[tid] += red[tid + s];
        __syncthreads();
    }
    v = red[0]; __syncthreads();
    return v;
}

// ---------------- init h = broadcast(init_hstate) ----------------
__global__ void init_h_kernel(const float* __restrict__ ih) {
    int idx = blockIdx.x * blockDim.x + threadIdx.x;
    if (idx < NN*DHH) g_h[idx] = ih[idx % DHH];
}

// ---------------- fused policy kernel: one block per sample ----------------
// repr -> pos/mage -> policy MLP -> logits(+mask) -> k-subset relaxation ->
// logprob -> controlled adjacency
__global__ __launch_bounds__(256)
void policy_kernel(const float* __restrict__ wr,  const float* __restrict__ br,
                   const float* __restrict__ wp,  const float* __restrict__ bp,
                   const float* __restrict__ wm,  const float* __restrict__ bm,
                   const float* __restrict__ wq1, const float* __restrict__ bq1,
                   const float* __restrict__ wq2, const float* __restrict__ bq2,
                   const float* __restrict__ amask, const float* __restrict__ gum,
                   const float* __restrict__ adjs,  float* __restrict__ logp_out,
                   int t)
{
    int n = blockIdx.x, tid = threadIdx.x;
    __shared__ float hs   [DHH];     // 25.6 KB
    __shared__ float e_s  [EE];
    __shared__ float cat_s[2*EE];
    __shared__ float hq_s [HPP];
    __shared__ float logit_s[LL];
    __shared__ float score_s[LL];
    __shared__ float sel_s  [LL];
    __shared__ float red_s  [256];

    const float* hn = g_h + (size_t)n * DHH;
    for (int i = tid; i < DHH; i += 256) hs[i] = hn[i];
    __syncthreads();

    // e = tanh(h_flat @ wr + br)  : 6400 -> 128
    if (tid < EE) {
        float a0 = 0.f, a1 = 0.f, a2 = 0.f, a3 = 0.f;
        for (int k = 0; k < DHH; k += 4) {
            a0 += hs[k+0] * wr[(k+0)*EE + tid];
            a1 += hs[k+1] * wr[(k+1)*EE + tid];
            a2 += hs[k+2] * wr[(k+2)*EE + tid];
            a3 += hs[k+3] * wr[(k+3)*EE + tid];
        }
        e_s[tid] = tanhf((a0 + a1) + (a2 + a3) + br[tid]);
    }
    __syncthreads();

    // pos (threads 0..127), mage (threads 128..255)
    {
        int j = tid & (EE - 1);
        const float* W = (tid < EE) ? wp : wm;
        const float* B = (tid < EE) ? bp : bm;
        float a = 0.f;
        #pragma unroll 4
        for (int k = 0; k < EE; k++) a += e_s[k] * W[k*EE + j];
        cat_s[tid] = a + B[j];
    }
    __syncthreads();

    // hq = tanh(cat @ wq1 + bq1) : 256 -> 256
    {
        float a = 0.f;
        #pragma unroll 4
        for (int k = 0; k < 2*EE; k++) a += cat_s[k] * wq1[k*HPP + tid];
        hq_s[tid] = tanhf(a + bq1[tid]);
    }
    __syncthreads();

    // logits = hq @ wq2 + bq2, then mask; init scores/sel
    for (int l = tid; l < LL; l += 256) {
        float a = 0.f;
        #pragma unroll 4
        for (int j = 0; j < HPP; j++) a += hq_s[j] * wq2[j*LL + l];
        a += bq2[l];
        float mk = amask[n*LL + l];
        a = mk * (-1e6f) + a * (1.f - mk);
        logit_s[l] = a;
        score_s[l] = a + gum[((size_t)n*TT + t)*LL + l];
        sel_s[l]   = 0.f;
    }
    __syncthreads();

    // relaxed top-K subset sampling
    for (int it = 0; it < KK; it++) {
        for (int l = tid; l < LL; l += 256) {
            float c = 1.f - sel_s[l];
            c = fminf(fmaxf(c, 1e-6f), 1.f);
            score_s[l] += logf(c);
        }
        __syncthreads();
        float m = -1e30f;
        for (int l = tid; l < LL; l += 256) m = fmaxf(m, score_s[l]);
        m = blk_max256(m, red_s, tid);
        float ps = 0.f;
        for (int l = tid; l < LL; l += 256) ps += expf(score_s[l] - m);
        ps = blk_sum256(ps, red_s, tid);
        float inv = 1.f / ps;
        for (int l = tid; l < LL; l += 256) sel_s[l] += expf(score_s[l] - m) * inv;
        __syncthreads();
    }
    // khot = clip(sel, 0, 1)
    for (int l = tid; l < LL; l += 256) sel_s[l] = fminf(fmaxf(sel_s[l], 0.f), 1.f);
    __syncthreads();

    // logprob = sum(khot * log_softmax(logits))
    float m2 = -1e30f;
    for (int l = tid; l < LL; l += 256) m2 = fmaxf(m2, logit_s[l]);
    m2 = blk_max256(m2, red_s, tid);
    float s2 = 0.f;
    for (int l = tid; l < LL; l += 256) s2 += expf(logit_s[l] - m2);
    s2 = blk_sum256(s2, red_s, tid);
    float lse = m2 + logf(s2);
    float lp = 0.f;
    for (int l = tid; l < LL; l += 256) lp += sel_s[l] * (logit_s[l] - lse);
    lp = blk_sum256(lp, red_s, tid);
    if (tid == 0) logp_out[n*TT + t] = lp;

    // adjacency with control applied: adj = adjs * (1 - ctrl)
    for (int idx = tid; idx < DD*DD; idx += 256) {
        int i = idx / DD, j = idx % DD;
        float ctrl = 0.f;
        if (i != j) {
            int jj = (j < i) ? j : j - 1;
            ctrl = sel_s[i*(DD-1) + jj];
        }
        g_adj[(size_t)n*DD*DD + idx] = adjs[idx] * (1.f - ctrl);
    }
}

// ---------------- jump kernel: h += tanh((adj@h)@wd + obs*wo + bd) ----------------
__global__ __launch_bounds__(256)
void jump_kernel(const float* __restrict__ wd, const float* __restrict__ bd,
                 const float* __restrict__ wo, const float* __restrict__ edata,
                 int t)
{
    int n = blockIdx.x, tid = threadIdx.x;   // tid = H column
    __shared__ float adj_s[DD*DD];
    __shared__ float ms   [DD*HH];           // m = adj @ h  (25 x 256)
    __shared__ float obs_s[DD];

    for (int i = tid; i < DD*DD; i += 256) adj_s[i] = g_adj[(size_t)n*DD*DD + i];
    if (tid < DD) obs_s[tid] = edata[((size_t)n*TT + t)*DD + tid];

    float* hn = g_h + (size_t)n * DHH;
    float hcol[DD];
    #pragma unroll
    for (int i = 0; i < DD; i++) hcol[i] = hn[i*HH + tid];
    __syncthreads();

    #pragma unroll
    for (int i = 0; i < DD; i++) {
        float a = 0.f;
        #pragma unroll
        for (int j = 0; j < DD; j++) a += adj_s[i*DD + j] * hcol[j];
        ms[i*HH + tid] = a;
    }
    __syncthreads();

    float acc[DD];
    float wot = wo[tid], bdt = bd[tid];
    #pragma unroll
    for (int i = 0; i < DD; i++) acc[i] = obs_s[i] * wot + bdt;
    for (int k = 0; k < HH; k++) {
        float w = wd[k*HH + tid];
        #pragma unroll
        for (int i = 0; i < DD; i++) acc[i] += ms[i*HH + k] * w;
    }
    #pragma unroll
    for (int i = 0; i < DD; i++) hn[i*HH + tid] = hcol[i] + tanhf(acc[i]);
}

// ---------------- generic fp32 GEMM, 64x64x16 tile, 256 threads, 4x4 per thread ----
// C[M,Nd] = A[M,Kd] @ W[Kd,Nd] (+bias, optional tanh / RK epilogues).
// A-load optionally fuses  A + alpha*(dt/RK)*kprev  (RK stage input).
// mode: 0 = C = tanh(v)                    (cfn layer 1)
//       1 = C = v; acc  = accw*v           (k1)
//       2 = C = v; acc += accw*v           (k2,k3)
//       3 = C(h) += (dt/(RK*6))*(acc + v)  (k4 + state update)
__global__ __launch_bounds__(256)
void gemm_kernel(const float* __restrict__ A, const float* __restrict__ kprev,
                 float alpha,
                 const float* __restrict__ W, const float* __restrict__ bias,
                 float* __restrict__ C, float* __restrict__ acc,
                 int mode, float accw,
                 const float* __restrict__ et, const float* __restrict__ t0,
                 int t, int Kd, int Nd)
{
    __shared__ float As[16][64];
    __shared__ float Ws[16][64];

    int tid = threadIdx.x;
    int tx = tid & 15, ty = tid >> 4;
    int rb = blockIdx.y * 64;
    int cb = blockIdx.x * 64;

    int lr = tid >> 2;             // 0..63 : tile row for A load
    int lk = (tid & 3) * 4;        // 0,4,8,12 : k offset for A load
    int wrw = tid >> 4;            // 0..15 : k row for W load
    int wcc = (tid & 15) * 4;      // col offset for W load

    int grow = rb + lr;
    float sA = 0.f;
    if (kprev) {
        int n = grow / DD;
        sA = alpha * get_dt(et, t0, n, t) / (float)RKN;
    }

    float accr[4][4];
    #pragma unroll
    for (int i = 0; i < 4; i++)
        #pragma unroll
        for (int j = 0; j < 4; j++) accr[i][j] = 0.f;

    for (int kb = 0; kb < Kd; kb += 16) {
        float4 av = *(const float4*)(A + (size_t)grow*Kd + kb + lk);
        if (kprev) {
            float4 kv = *(const float4*)(kprev + (size_t)grow*Kd + kb + lk);
            av.x += sA*kv.x; av.y += sA*kv.y; av.z += sA*kv.z; av.w += sA*kv.w;
        }
        As[lk+0][lr] = av.x; As[lk+1][lr] = av.y;
        As[lk+2][lr] = av.z; As[lk+3][lr] = av.w;
        *(float4*)&Ws[wrw][wcc] = *(const float4*)(W + (size_t)(kb + wrw)*Nd + cb + wcc);
        __syncthreads();

        #pragma unroll
        for (int k = 0; k < 16; k++) {
            float4 af = *(const float4*)&As[k][ty*4];
            float4 bf = *(const float4*)&Ws[k][tx*4];
            accr[0][0] += af.x*bf.x; accr[0][1] += af.x*bf.y;
            accr[0][2] += af.x*bf.z; accr[0][3] += af.x*bf.w;
            accr[1][0] += af.y*bf.x; accr[1][1] += af.y*bf.y;
            accr[1][2] += af.y*bf.z; accr[1][3] += af.y*bf.w;
            accr[2][0] += af.z*bf.x; accr[2][1] += af.z*bf.y;
            accr[2][2] += af.z*bf.z; accr[2][3] += af.z*bf.w;
            accr[3][0] += af.w*bf.x; accr[3][1] += af.w*bf.y;
            accr[3][2] += af.w*bf.z; accr[3][3] += af.w*bf.w;
        }
        __syncthreads();
    }

    #pragma unroll
    for (int i = 0; i < 4; i++) {
        int row = rb + ty*4 + i;
        float s6 = 0.f;
        if (mode == 3) {
            int n = row / DD;
            s6 = get_dt(et, t0, n, t) / (float)(RKN * 6);
        }
        #pragma unroll
        for (int j = 0; j < 4; j++) {
            int col = cb + tx*4 + j;
            float v = accr[i][j] + bias[col];
            size_t idx = (size_t)row*Nd + col;
            if (mode == 0)      C[idx] = tanhf(v);
            else if (mode == 1) { C[idx] = v; acc[idx] = accw * v; }
            else if (mode == 2) { C[idx] = v; acc[idx] += accw * v; }
            else                C[idx] += s6 * (acc[idx] + v);   // C == g_h
        }
    }
}

// ---------------- intensity: softplus(tanh(h@wi1+bi1)@wi2+bi2) ----------------
__global__ __launch_bounds__(128)
void intensity_kernel(const float* __restrict__ wi1, const float* __restrict__ bi1,
                      const float* __restrict__ wi2, const float* __restrict__ bi2,
                      float* __restrict__ out, int t)
{
    int row = blockIdx.x;          // 0..3199  (n*D + d)
    int tid = threadIdx.x;         // 128
    int n = row / DD, d = row % DD;
    __shared__ float hrow[HH];
    __shared__ float red[128];
    for (int i = tid; i < HH; i += 128) hrow[i] = g_h[(size_t)row*HH + i];
    __syncthreads();
    float a = 0.f;
    #pragma unroll 4
    for (int k = 0; k < HH; k++) a += hrow[k] * wi1[k*HII + tid];
    float tj = tanhf(a + bi1[tid]);
    red[tid] = tj * wi2[tid];
    __syncthreads();
    #pragma unroll
    for (int s = 64; s > 0; s >>= 1) {
        if (tid < s) red[tid] += red[tid + s];
        __syncthreads();
    }
    if (tid == 0) {
        float x = red[0] + bi2[0];
        float sp = fmaxf(x, 0.f) + log1pf(expf(-fabsf(x)));
        out[((size_t)n*TT + t)*DD + d] = sp;
    }
}

// ---------------- launch ----------------
extern "C" void kernel_launch(void* const* d_in, const int* in_sizes, int n_in,
                              void* d_out, int out_size)
{
    const float* event_time = (const float*)d_in[0];
    const float* event_data = (const float*)d_in[1];
    const float* t0     = (const float*)d_in[2];
    const float* amask  = (const float*)d_in[3];
    const float* gum    = (const float*)d_in[4];
    const float* init_h = (const float*)d_in[5];
    const float* adjs   = (const float*)d_in[6];
    const float* wc1 = (const float*)d_in[7];  const float* bc1 = (const float*)d_in[8];
    const float* wc2 = (const float*)d_in[9];  const float* bc2 = (const float*)d_in[10];
    const float* wd  = (const float*)d_in[11]; const float* bd  = (const float*)d_in[12];
    const float* wo  = (const float*)d_in[13];
    const float* wi1 = (const float*)d_in[14]; const float* bi1 = (const float*)d_in[15];
    const float* wi2 = (const float*)d_in[16]; const float* bi2 = (const float*)d_in[17];
    const float* wr  = (const float*)d_in[18]; const float* br  = (const float*)d_in[19];
    const float* wp  = (const float*)d_in[20]; const float* bp  = (const float*)d_in[21];
    const float* wm  = (const float*)d_in[22]; const float* bm  = (const float*)d_in[23];
    const float* wq1 = (const float*)d_in[24]; const float* bq1 = (const float*)d_in[25];
    const float* wq2 = (const float*)d_in[26]; const float* bq2 = (const float*)d_in[27];

    float* out      = (float*)d_out;
    float* out_logp = out + (size_t)NN*TT*DD;

    void* p;
    cudaGetSymbolAddress(&p, g_h);    float* h  = (float*)p;
    cudaGetSymbolAddress(&p, g_t1);   float* t1 = (float*)p;
    cudaGetSymbolAddress(&p, g_kcur); float* kc = (float*)p;
    cudaGetSymbolAddress(&p, g_acc);  float* ac = (float*)p;

    init_h_kernel<<<(NN*DHH + 255)/256, 256>>>(init_h);

    const float alphas[4] = {0.f, 0.5f, 0.5f, 1.f};
    for (int t = 0; t < TT; t++) {
        policy_kernel<<<NN, 256>>>(wr, br, wp, bp, wm, bm, wq1, bq1, wq2, bq2,
                                   amask, gum, adjs, out_logp, t);
        jump_kernel<<<NN, 256>>>(wd, bd, wo, event_data, t);
        for (int r = 0; r < RKN; r++) {
            for (int s = 0; s < 4; s++) {
                const float* kprev = (s == 0) ? nullptr : kc;
                // layer 1: t1 = tanh(in @ wc1 + bc1), in = h + alpha*s_n*kprev
                gemm_kernel<<<dim3(HCC/64, NDD/64), 256>>>(
                    h, kprev, alphas[s], wc1, bc1, t1, nullptr, 0, 0.f,
                    event_time, t0, t, HH, HCC);
                // layer 2: k = t1 @ wc2 + bc2, RK epilogue
                int   mode = (s == 0) ? 1 : (s == 3) ? 3 : 2;
                float w    = (s == 1 || s == 2) ? 2.f : 1.f;
                float* Cp  = (s == 3) ? h : kc;
                gemm_kernel<<<dim3(HH/64, NDD/64), 256>>>(
                    t1, nullptr, 0.f, wc2, bc2, Cp, ac, mode, w,
                    event_time, t0, t, HCC, HH);
            }
        }
        intensity_kernel<<<NDD, 128>>>(wi1, bi1, wi2, bi2, out, t);
    }
}

// round 3
// speedup vs baseline: 1.1309x; 1.1309x over previous
#include <cuda_runtime.h>
#include <cuda_pipeline.h>
#include <math.h>

// ---------------- problem dims ----------------
#define NN   128
#define TT   16
#define DD   25
#define HH   256
#define HCC  512
#define HII  128
#define EE   128
#define HPP  256
#define LL   608          // D*(D-1)+8
#define KK   8
#define RKN  2
#define DHH  (DD*HH)      // 6400
#define P1KS 32           // split-K factor for e-GEMM
#define P1KC 200          // 6400/32

// ---------------- persistent device scratch ----------------
__device__ float g_h    [NN*DHH];          // state h (N,D,H)
__device__ float g_adj  [NN*DD*DD];        // per-sample controlled adjacency
__device__ float g_epart[P1KS*NN*EE];      // split-K partials for e
__device__ float g_e    [NN*EE];           // e = tanh(hflat @ wr + br)

// ---------------- helpers ----------------
__device__ __forceinline__ void cp_tile(float* dst, const float* src, int nf4, int tid) {
    const float4* s4 = (const float4*)src;
    float4* d4 = (float4*)dst;
    for (int p = tid; p < nf4; p += 256)
        __pipeline_memcpy_async(&d4[p], &s4[p], 16);
    __pipeline_commit();
}

__device__ __forceinline__ float blk_max256(float v, float* red, int tid) {
    red[tid] = v; __syncthreads();
    #pragma unroll
    for (int s = 128; s > 0; s >>= 1) {
        if (tid < s) red[tid] = fmaxf(red[tid], red[tid + s]);
        __syncthreads();
    }
    v = red[0]; __syncthreads();
    return v;
}
__device__ __forceinline__ float blk_sum256(float v, float* red, int tid) {
    red[tid] = v; __syncthreads();
    #pragma unroll
    for (int s = 128; s > 0; s >>= 1) {
        if (tid < s) red[tid] += red[tid + s];
        __syncthreads();
    }
    v = red[0]; __syncthreads();
    return v;
}

#define FMA8(av, W0, W1, A, base) \
    A[base+0] = fmaf(av, W0.x, A[base+0]); \
    A[base+1] = fmaf(av, W0.y, A[base+1]); \
    A[base+2] = fmaf(av, W0.z, A[base+2]); \
    A[base+3] = fmaf(av, W0.w, A[base+3]); \
    A[base+4] = fmaf(av, W1.x, A[base+4]); \
    A[base+5] = fmaf(av, W1.y, A[base+5]); \
    A[base+6] = fmaf(av, W1.z, A[base+6]); \
    A[base+7] = fmaf(av, W1.w, A[base+7]);

// ---------------- init h = broadcast(init_hstate) ----------------
__global__ void init_h_kernel(const float* __restrict__ ih) {
    int idx = blockIdx.x * blockDim.x + threadIdx.x;
    if (idx < NN*DHH) g_h[idx] = ih[idx % DHH];
}

// ---------------- P1: e partials, split-K GEMM  (128x6400 @ 6400x128) ------
__global__ __launch_bounds__(256)
void e_gemm_kernel(const float* __restrict__ wr)
{
    __shared__ float sa[8][64];
    __shared__ float sb[8][64];
    int tid = threadIdx.x;
    int tx = tid & 15, ty = tid >> 4;
    int rb = blockIdx.y * 64, cb = blockIdx.x * 64;
    int k0 = blockIdx.z * P1KC;

    float acc[4][4];
    #pragma unroll
    for (int i = 0; i < 4; i++)
        #pragma unroll
        for (int j = 0; j < 4; j++) acc[i][j] = 0.f;

    int r  = tid >> 2, kk  = (tid & 3) * 2;
    int k2 = tid >> 5, c2  = (tid & 31) * 2;

    for (int kb = 0; kb < P1KC; kb += 8) {
        float2 av = *(const float2*)&g_h[(size_t)(rb + r)*DHH + k0 + kb + kk];
        sa[kk][r] = av.x; sa[kk+1][r] = av.y;
        float2 wv = *(const float2*)&wr[(size_t)(k0 + kb + k2)*EE + cb + c2];
        sb[k2][c2] = wv.x; sb[k2][c2+1] = wv.y;
        __syncthreads();
        #pragma unroll
        for (int k = 0; k < 8; k++) {
            float4 a4 = *(const float4*)&sa[k][ty*4];
            float4 b4 = *(const float4*)&sb[k][tx*4];
            acc[0][0] += a4.x*b4.x; acc[0][1] += a4.x*b4.y; acc[0][2] += a4.x*b4.z; acc[0][3] += a4.x*b4.w;
            acc[1][0] += a4.y*b4.x; acc[1][1] += a4.y*b4.y; acc[1][2] += a4.y*b4.z; acc[1][3] += a4.y*b4.w;
            acc[2][0] += a4.z*b4.x; acc[2][1] += a4.z*b4.y; acc[2][2] += a4.z*b4.z; acc[2][3] += a4.z*b4.w;
            acc[3][0] += a4.w*b4.x; acc[3][1] += a4.w*b4.y; acc[3][2] += a4.w*b4.z; acc[3][3] += a4.w*b4.w;
        }
        __syncthreads();
    }
    float* dst = g_epart + (size_t)blockIdx.z * (NN*EE);
    #pragma unroll
    for (int i = 0; i < 4; i++)
        #pragma unroll
        for (int j = 0; j < 4; j++)
            dst[(rb + ty*4 + i)*EE + cb + tx*4 + j] = acc[i][j];
}

// ---------------- P1r: reduce partials + tanh(+br) ----------------
__global__ __launch_bounds__(256)
void e_reduce_kernel(const float* __restrict__ br)
{
    int i = blockIdx.x * 256 + threadIdx.x;     // 16384 total
    float s = 0.f;
    #pragma unroll
    for (int k = 0; k < P1KS; k++) s += g_epart[(size_t)k*(NN*EE) + i];
    g_e[i] = tanhf(s + br[i & (EE-1)]);
}

// ---------------- P2: policy (per sample) ----------------
__global__ __launch_bounds__(256)
void policy_kernel(const float* __restrict__ wp,  const float* __restrict__ bp,
                   const float* __restrict__ wm,  const float* __restrict__ bm,
                   const float* __restrict__ wq1, const float* __restrict__ bq1,
                   const float* __restrict__ wq2, const float* __restrict__ bq2,
                   const float* __restrict__ amask, const float* __restrict__ gum,
                   const float* __restrict__ adjs,  float* __restrict__ logp_out,
                   int t)
{
    int n = blockIdx.x, tid = threadIdx.x;
    __shared__ float e_s  [EE];
    __shared__ float cat_s[2*EE];
    __shared__ float hq_s [HPP];
    __shared__ float logit_s[LL];
    __shared__ float score_s[LL];
    __shared__ float sel_s  [LL];
    __shared__ float red_s  [256];

    if (tid < EE) e_s[tid] = g_e[n*EE + tid];
    __syncthreads();

    // pos (threads 0..127), mage (threads 128..255)
    {
        int j = tid & (EE - 1);
        const float* W = (tid < EE) ? wp : wm;
        const float* B = (tid < EE) ? bp : bm;
        float a = 0.f;
        #pragma unroll 4
        for (int k = 0; k < EE; k++) a += e_s[k] * W[k*EE + j];
        cat_s[tid] = a + B[j];
    }
    __syncthreads();

    // hq = tanh(cat @ wq1 + bq1)
    {
        float a = 0.f;
        #pragma unroll 4
        for (int k = 0; k < 2*EE; k++) a += cat_s[k] * wq1[k*HPP + tid];
        hq_s[tid] = tanhf(a + bq1[tid]);
    }
    __syncthreads();

    // logits + mask; init scores/sel
    for (int l = tid; l < LL; l += 256) {
        float a = 0.f;
        #pragma unroll 4
        for (int j = 0; j < HPP; j++) a += hq_s[j] * wq2[j*LL + l];
        a += bq2[l];
        float mk = amask[n*LL + l];
        a = mk * (-1e6f) + a * (1.f - mk);
        logit_s[l] = a;
        score_s[l] = a + gum[((size_t)n*TT + t)*LL + l];
        sel_s[l]   = 0.f;
    }
    __syncthreads();

    for (int it = 0; it < KK; it++) {
        for (int l = tid; l < LL; l += 256) {
            float c = 1.f - sel_s[l];
            c = fminf(fmaxf(c, 1e-6f), 1.f);
            score_s[l] += logf(c);
        }
        __syncthreads();
        float m = -1e30f;
        for (int l = tid; l < LL; l += 256) m = fmaxf(m, score_s[l]);
        m = blk_max256(m, red_s, tid);
        float ps = 0.f;
        for (int l = tid; l < LL; l += 256) ps += expf(score_s[l] - m);
        ps = blk_sum256(ps, red_s, tid);
        float inv = 1.f / ps;
        for (int l = tid; l < LL; l += 256) sel_s[l] += expf(score_s[l] - m) * inv;
        __syncthreads();
    }
    for (int l = tid; l < LL; l += 256) sel_s[l] = fminf(fmaxf(sel_s[l], 0.f), 1.f);
    __syncthreads();

    float m2 = -1e30f;
    for (int l = tid; l < LL; l += 256) m2 = fmaxf(m2, logit_s[l]);
    m2 = blk_max256(m2, red_s, tid);
    float s2 = 0.f;
    for (int l = tid; l < LL; l += 256) s2 += expf(logit_s[l] - m2);
    s2 = blk_sum256(s2, red_s, tid);
    float lse = m2 + logf(s2);
    float lp = 0.f;
    for (int l = tid; l < LL; l += 256) lp += sel_s[l] * (logit_s[l] - lse);
    lp = blk_sum256(lp, red_s, tid);
    if (tid == 0) logp_out[n*TT + t] = lp;

    for (int idx = tid; idx < DD*DD; idx += 256) {
        int i = idx / DD, j = idx % DD;
        float ctrl = 0.f;
        if (i != j) {
            int jj = (j < i) ? j : j - 1;
            ctrl = sel_s[i*(DD-1) + jj];
        }
        g_adj[(size_t)n*DD*DD + idx] = adjs[idx] * (1.f - ctrl);
    }
}

// ---------------- jump: h += tanh((adj@h)@wd + obs*wo + bd) ----------------
__global__ __launch_bounds__(256)
void jump_kernel(const float* __restrict__ wd, const float* __restrict__ bd,
                 const float* __restrict__ wo, const float* __restrict__ edata,
                 int t)
{
    int n = blockIdx.x, tid = threadIdx.x;   // tid = H column
    __shared__ float adj_s[DD*DD];
    __shared__ float ms   [DD*HH];
    __shared__ float obs_s[DD];

    for (int i = tid; i < DD*DD; i += 256) adj_s[i] = g_adj[(size_t)n*DD*DD + i];
    if (tid < DD) obs_s[tid] = edata[((size_t)n*TT + t)*DD + tid];

    float* hn = g_h + (size_t)n * DHH;
    float hcol[DD];
    #pragma unroll
    for (int i = 0; i < DD; i++) hcol[i] = hn[i*HH + tid];
    __syncthreads();

    #pragma unroll
    for (int i = 0; i < DD; i++) {
        float a = 0.f;
        #pragma unroll
        for (int j = 0; j < DD; j++) a += adj_s[i*DD + j] * hcol[j];
        ms[i*HH + tid] = a;
    }
    __syncthreads();

    float acc[DD];
    float wot = wo[tid], bdt = bd[tid];
    #pragma unroll
    for (int i = 0; i < DD; i++) acc[i] = obs_s[i] * wot + bdt;
    for (int k = 0; k < HH; k++) {
        float w = wd[k*HH + tid];
        #pragma unroll
        for (int i = 0; i < DD; i++) acc[i] += ms[i*HH + k] * w;
    }
    #pragma unroll
    for (int i = 0; i < DD; i++) hn[i*HH + tid] = hcol[i] + tanhf(acc[i]);
}

// ---------------- fused ODE integrator + intensity, one block per sample ----
// smem layout (floats): h[8192] | in[8192] | acc[8192] | t1[16384] | w[2*8192]
#define ODE_SMEM_BYTES 229376

__global__ __launch_bounds__(256, 1)
void ode_kernel(const float* __restrict__ wc1, const float* __restrict__ bc1,
                const float* __restrict__ wc2, const float* __restrict__ bc2,
                const float* __restrict__ wi1, const float* __restrict__ bi1,
                const float* __restrict__ wi2, const float* __restrict__ bi2,
                const float* __restrict__ et,  const float* __restrict__ t0v,
                float* __restrict__ out, int t)
{
    extern __shared__ float sm[];
    float* sh_h  = sm;
    float* sh_in = sm + 8192;
    float* sh_ac = sm + 16384;
    float* sh_t1 = sm + 24576;
    float* sh_w  = sm + 40960;     // two 8192-float buffers

    int n = blockIdx.x, tid = threadIdx.x;

    for (int i = tid; i < 8192; i += 256) {
        int r = i >> 8;
        float v = (r < DD) ? g_h[(size_t)n*DHH + i] : 0.f;
        sh_h[i] = v; sh_in[i] = v;
    }
    float tp  = (t == 0) ? t0v[n] : et[n*TT + t - 1];
    float sdt = (et[n*TT + t] - tp) * (1.f / RKN);
    __syncthreads();

    const int rgA = tid >> 6, cgA = tid & 63;   // A: rows 8rgA+, cols 8cgA+
    const int rgB = tid >> 5, cgB = tid & 31;   // B: rows 4rgB+, cols 8cgB+

    for (int rk = 0; rk < RKN; rk++)
    for (int s = 0; s < 4; s++) {
        // ===== stage A: t1 = tanh(in @ wc1 + bc1)   (32x256)@(256x512)
        {
            float acc[64];
            #pragma unroll
            for (int q = 0; q < 64; q++) acc[q] = 0.f;
            cp_tile(sh_w, wc1, 2048, tid);
            for (int kb = 0; kb < 16; kb++) {
                if (kb + 1 < 16)
                    cp_tile(sh_w + ((kb+1)&1)*8192, wc1 + (kb+1)*16*HCC, 2048, tid);
                if (kb + 1 < 16) __pipeline_wait_prior(1); else __pipeline_wait_prior(0);
                __syncthreads();
                const float* wb  = sh_w + (kb&1)*8192;
                const float* inb = sh_in + kb*16;
                #pragma unroll 4
                for (int k = 0; k < 16; k++) {
                    float4 w0 = *(const float4*)&wb[k*HCC + cgA*8];
                    float4 w1 = *(const float4*)&wb[k*HCC + cgA*8 + 4];
                    #pragma unroll
                    for (int i = 0; i < 8; i++) {
                        float a = inb[(rgA*8 + i)*HH + k];
                        FMA8(a, w0, w1, acc, i*8);
                    }
                }
                __syncthreads();
            }
            #pragma unroll
            for (int j = 0; j < 8; j++) {
                float b = bc1[cgA*8 + j];
                #pragma unroll
                for (int i = 0; i < 8; i++)
                    sh_t1[(rgA*8 + i)*HCC + cgA*8 + j] = tanhf(acc[i*8 + j] + b);
            }
            __syncthreads();
        }
        // ===== stage B: kv = t1 @ wc2 + bc2   (32x512)@(512x256), RK epilogue
        {
            float acc[32];
            #pragma unroll
            for (int q = 0; q < 32; q++) acc[q] = 0.f;
            cp_tile(sh_w, wc2, 1024, tid);
            for (int kb = 0; kb < 32; kb++) {
                if (kb + 1 < 32)
                    cp_tile(sh_w + ((kb+1)&1)*8192, wc2 + (kb+1)*16*HH, 1024, tid);
                if (kb + 1 < 32) __pipeline_wait_prior(1); else __pipeline_wait_prior(0);
                __syncthreads();
                const float* wb = sh_w + (kb&1)*8192;
                const float* tb = sh_t1 + kb*16;
                #pragma unroll 4
                for (int k = 0; k < 16; k++) {
                    float4 w0 = *(const float4*)&wb[k*HH + cgB*8];
                    float4 w1 = *(const float4*)&wb[k*HH + cgB*8 + 4];
                    #pragma unroll
                    for (int i = 0; i < 4; i++) {
                        float a = tb[(rgB*4 + i)*HCC + k];
                        FMA8(a, w0, w1, acc, i*8);
                    }
                }
                __syncthreads();
            }
            #pragma unroll
            for (int i = 0; i < 4; i++) {
                int r = rgB*4 + i;
                #pragma unroll
                for (int j = 0; j < 8; j++) {
                    int c = cgB*8 + j;
                    float kv = acc[i*8 + j] + bc2[c];
                    int idx = r*HH + c;
                    if (s == 0)      { sh_ac[idx] = kv;        sh_in[idx] = sh_h[idx] + 0.5f*sdt*kv; }
                    else if (s == 1) { sh_ac[idx] += 2.f*kv;   sh_in[idx] = sh_h[idx] + 0.5f*sdt*kv; }
                    else if (s == 2) { sh_ac[idx] += 2.f*kv;   sh_in[idx] = sh_h[idx] + sdt*kv; }
                    else             { float hn = sh_h[idx] + (sdt*(1.f/6.f))*(sh_ac[idx] + kv);
                                       sh_h[idx] = hn; sh_in[idx] = hn; }
                }
            }
            __syncthreads();
        }
    }

    // write back h
    for (int i = tid; i < DHH; i += 256) g_h[(size_t)n*DHH + i] = sh_h[i];

    // ===== intensity: softplus( tanh(h@wi1+bi1) @ wi2 + bi2 )
    {
        float acc[16];
        #pragma unroll
        for (int q = 0; q < 16; q++) acc[q] = 0.f;
        const int rgI = tid >> 5, cgI = tid & 31;   // rows 4rgI+, cols 4cgI+
        cp_tile(sh_w, wi1, 512, tid);
        for (int kb = 0; kb < 16; kb++) {
            if (kb + 1 < 16)
                cp_tile(sh_w + ((kb+1)&1)*8192, wi1 + (kb+1)*16*HII, 512, tid);
            if (kb + 1 < 16) __pipeline_wait_prior(1); else __pipeline_wait_prior(0);
            __syncthreads();
            const float* wb = sh_w + (kb&1)*8192;
            #pragma unroll 4
            for (int k = 0; k < 16; k++) {
                float4 w = *(const float4*)&wb[k*HII + cgI*4];
                #pragma unroll
                for (int i = 0; i < 4; i++) {
                    float a = sh_h[(rgI*4 + i)*HH + kb*16 + k];
                    acc[i*4+0] = fmaf(a, w.x, acc[i*4+0]);
                    acc[i*4+1] = fmaf(a, w.y, acc[i*4+1]);
                    acc[i*4+2] = fmaf(a, w.z, acc[i*4+2]);
                    acc[i*4+3] = fmaf(a, w.w, acc[i*4+3]);
                }
            }
            __syncthreads();
        }
        #pragma unroll
        for (int j = 0; j < 4; j++) {
            int c = cgI*4 + j;
            float b = bi1[c], wv = wi2[c];
            #pragma unroll
            for (int i = 0; i < 4; i++)
                sh_t1[(rgI*4 + i)*HII + c] = tanhf(acc[i*4 + j] + b) * wv;
        }
        __syncthreads();
        if (tid < DD) {
            float ssum = 0.f;
            for (int j = 0; j < HII; j++) ssum += sh_t1[tid*HII + j];
            float x = ssum + bi2[0];
            float sp = fmaxf(x, 0.f) + log1pf(expf(-fabsf(x)));
            out[((size_t)n*TT + t)*DD + tid] = sp;
        }
    }
}

// ---------------- launch ----------------
extern "C" void kernel_launch(void* const* d_in, const int* in_sizes, int n_in,
                              void* d_out, int out_size)
{
    const float* event_time = (const float*)d_in[0];
    const float* event_data = (const float*)d_in[1];
    const float* t0     = (const float*)d_in[2];
    const float* amask  = (const float*)d_in[3];
    const float* gum    = (const float*)d_in[4];
    const float* init_h = (const float*)d_in[5];
    const float* adjs   = (const float*)d_in[6];
    const float* wc1 = (const float*)d_in[7];  const float* bc1 = (const float*)d_in[8];
    const float* wc2 = (const float*)d_in[9];  const float* bc2 = (const float*)d_in[10];
    const float* wd  = (const float*)d_in[11]; const float* bd  = (const float*)d_in[12];
    const float* wo  = (const float*)d_in[13];
    const float* wi1 = (const float*)d_in[14]; const float* bi1 = (const float*)d_in[15];
    const float* wi2 = (const float*)d_in[16]; const float* bi2 = (const float*)d_in[17];
    const float* wr  = (const float*)d_in[18]; const float* br  = (const float*)d_in[19];
    const float* wp  = (const float*)d_in[20]; const float* bp  = (const float*)d_in[21];
    const float* wm  = (const float*)d_in[22]; const float* bm  = (const float*)d_in[23];
    const float* wq1 = (const float*)d_in[24]; const float* bq1 = (const float*)d_in[25];
    const float* wq2 = (const float*)d_in[26]; const float* bq2 = (const float*)d_in[27];

    float* out      = (float*)d_out;
    float* out_logp = out + (size_t)NN*TT*DD;

    cudaFuncSetAttribute(ode_kernel, cudaFuncAttributeMaxDynamicSharedMemorySize,
                         ODE_SMEM_BYTES);

    init_h_kernel<<<(NN*DHH + 255)/256, 256>>>(init_h);

    for (int t = 0; t < TT; t++) {
        e_gemm_kernel<<<dim3(2, 2, P1KS), 256>>>(wr);
        e_reduce_kernel<<<(NN*EE)/256, 256>>>(br);
        policy_kernel<<<NN, 256>>>(wp, bp, wm, bm, wq1, bq1, wq2, bq2,
                                   amask, gum, adjs, out_logp, t);
        jump_kernel<<<NN, 256>>>(wd, bd, wo, event_data, t);
        ode_kernel<<<NN, 256, ODE_SMEM_BYTES>>>(wc1, bc1, wc2, bc2,
                                                wi1, bi1, wi2, bi2,
                                                event_time, t0, out, t);
    }
}

// round 4
// speedup vs baseline: 1.3162x; 1.1639x over previous
#include <cuda_runtime.h>
#include <cuda_pipeline.h>
#include <math.h>

// ---------------- problem dims ----------------
#define NN   128
#define TT   16
#define DD   25
#define HH   256
#define HCC  512
#define HII  128
#define EE   128
#define HPP  256
#define LL   608          // D*(D-1)+8
#define KK   8
#define RKN  2
#define DHH  (DD*HH)      // 6400
#define P1KS 32           // split-K factor for e-GEMM
#define P1KC 200          // 6400/32

// ---------------- persistent device scratch ----------------
__device__ float g_h     [NN*DHH];         // state h (N,D,H)
__device__ float g_adj   [NN*DD*DD];       // per-sample controlled adjacency
__device__ float g_epart [P1KS*NN*EE];     // split-K partials for e
__device__ float g_e     [NN*EE];          // e = tanh(hflat @ wr + br)
__device__ float g_cat   [NN*2*EE];        // [pos | mage] (128 x 256)
__device__ float g_hq    [NN*HPP];         // tanh policy hidden (128 x 256)
__device__ float g_logit [NN*LL];          // masked logits (128 x 608)

// ---------------- helpers ----------------
__device__ __forceinline__ void cp_tile(float* dst, const float* src, int nf4, int tid) {
    const float4* s4 = (const float4*)src;
    float4* d4 = (float4*)dst;
    for (int p = tid; p < nf4; p += 256)
        __pipeline_memcpy_async(&d4[p], &s4[p], 16);
    __pipeline_commit();
}

__device__ __forceinline__ float blk_max256(float v, float* red, int tid) {
    red[tid] = v; __syncthreads();
    #pragma unroll
    for (int s = 128; s > 0; s >>= 1) {
        if (tid < s) red[tid] = fmaxf(red[tid], red[tid + s]);
        __syncthreads();
    }
    v = red[0]; __syncthreads();
    return v;
}
__device__ __forceinline__ float blk_sum256(float v, float* red, int tid) {
    red[tid] = v; __syncthreads();
    #pragma unroll
    for (int s = 128; s > 0; s >>= 1) {
        if (tid < s) red[tid] += red[tid + s];
        __syncthreads();
    }
    v = red[0]; __syncthreads();
    return v;
}

#define FMA8(av, W0, W1, A, base) \
    A[base+0] = fmaf(av, W0.x, A[base+0]); \
    A[base+1] = fmaf(av, W0.y, A[base+1]); \
    A[base+2] = fmaf(av, W0.z, A[base+2]); \
    A[base+3] = fmaf(av, W0.w, A[base+3]); \
    A[base+4] = fmaf(av, W1.x, A[base+4]); \
    A[base+5] = fmaf(av, W1.y, A[base+5]); \
    A[base+6] = fmaf(av, W1.z, A[base+6]); \
    A[base+7] = fmaf(av, W1.w, A[base+7]);

// ---------------- init h = broadcast(init_hstate) ----------------
__global__ void init_h_kernel(const float* __restrict__ ih) {
    int idx = blockIdx.x * blockDim.x + threadIdx.x;
    if (idx < NN*DHH) g_h[idx] = ih[idx % DHH];
}

// ---------------- P1: e partials, split-K GEMM  (128x6400 @ 6400x128) ------
__global__ __launch_bounds__(256)
void e_gemm_kernel(const float* __restrict__ wr)
{
    __shared__ float sa[8][64];
    __shared__ float sb[8][64];
    int tid = threadIdx.x;
    int tx = tid & 15, ty = tid >> 4;
    int rb = blockIdx.y * 64, cb = blockIdx.x * 64;
    int k0 = blockIdx.z * P1KC;

    float acc[4][4];
    #pragma unroll
    for (int i = 0; i < 4; i++)
        #pragma unroll
        for (int j = 0; j < 4; j++) acc[i][j] = 0.f;

    int r  = tid >> 2, kk  = (tid & 3) * 2;
    int k2 = tid >> 5, c2  = (tid & 31) * 2;

    for (int kb = 0; kb < P1KC; kb += 8) {
        float2 av = *(const float2*)&g_h[(size_t)(rb + r)*DHH + k0 + kb + kk];
        sa[kk][r] = av.x; sa[kk+1][r] = av.y;
        float2 wv = *(const float2*)&wr[(size_t)(k0 + kb + k2)*EE + cb + c2];
        sb[k2][c2] = wv.x; sb[k2][c2+1] = wv.y;
        __syncthreads();
        #pragma unroll
        for (int k = 0; k < 8; k++) {
            float4 a4 = *(const float4*)&sa[k][ty*4];
            float4 b4 = *(const float4*)&sb[k][tx*4];
            acc[0][0] += a4.x*b4.x; acc[0][1] += a4.x*b4.y; acc[0][2] += a4.x*b4.z; acc[0][3] += a4.x*b4.w;
            acc[1][0] += a4.y*b4.x; acc[1][1] += a4.y*b4.y; acc[1][2] += a4.y*b4.z; acc[1][3] += a4.y*b4.w;
            acc[2][0] += a4.z*b4.x; acc[2][1] += a4.z*b4.y; acc[2][2] += a4.z*b4.z; acc[2][3] += a4.z*b4.w;
            acc[3][0] += a4.w*b4.x; acc[3][1] += a4.w*b4.y; acc[3][2] += a4.w*b4.z; acc[3][3] += a4.w*b4.w;
        }
        __syncthreads();
    }
    float* dst = g_epart + (size_t)blockIdx.z * (NN*EE);
    #pragma unroll
    for (int i = 0; i < 4; i++)
        #pragma unroll
        for (int j = 0; j < 4; j++)
            dst[(rb + ty*4 + i)*EE + cb + tx*4 + j] = acc[i][j];
}

// ---------------- P1r: reduce partials + tanh(+br) ----------------
__global__ __launch_bounds__(256)
void e_reduce_kernel(const float* __restrict__ br)
{
    int i = blockIdx.x * 256 + threadIdx.x;     // 16384 total
    float s = 0.f;
    #pragma unroll
    for (int k = 0; k < P1KS; k++) s += g_epart[(size_t)k*(NN*EE) + i];
    g_e[i] = tanhf(s + br[i & (EE-1)]);
}

// ---------------- small batched GEMM, 64x64 tile, K param, optional tanh ----
// C[128, ldc] tile = A[128, lda] @ W[Kd, ldw] + bias   (tile cols are within W)
__global__ __launch_bounds__(256)
void gemm64_kernel(const float* __restrict__ A, int lda,
                   const float* __restrict__ W, int ldw,
                   const float* __restrict__ bias,
                   float* __restrict__ C, int ldc,
                   int Kd, int act)
{
    __shared__ float as[16][64];
    __shared__ float ws[16][64];
    int tid = threadIdx.x;
    int tx = tid & 15, ty = tid >> 4;
    int rb = blockIdx.y * 64, cb = blockIdx.x * 64;

    float acc[4][4];
    #pragma unroll
    for (int i = 0; i < 4; i++)
        #pragma unroll
        for (int j = 0; j < 4; j++) acc[i][j] = 0.f;

    int lr = tid >> 2, lk = (tid & 3) * 4;
    int wrw = tid >> 4, wcc = (tid & 15) * 4;

    for (int kb = 0; kb < Kd; kb += 16) {
        float4 av = *(const float4*)(A + (size_t)(rb + lr)*lda + kb + lk);
        as[lk+0][lr] = av.x; as[lk+1][lr] = av.y;
        as[lk+2][lr] = av.z; as[lk+3][lr] = av.w;
        *(float4*)&ws[wrw][wcc] = *(const float4*)(W + (size_t)(kb + wrw)*ldw + cb + wcc);
        __syncthreads();
        #pragma unroll
        for (int k = 0; k < 16; k++) {
            float4 a4 = *(const float4*)&as[k][ty*4];
            float4 b4 = *(const float4*)&ws[k][tx*4];
            acc[0][0] += a4.x*b4.x; acc[0][1] += a4.x*b4.y; acc[0][2] += a4.x*b4.z; acc[0][3] += a4.x*b4.w;
            acc[1][0] += a4.y*b4.x; acc[1][1] += a4.y*b4.y; acc[1][2] += a4.y*b4.z; acc[1][3] += a4.y*b4.w;
            acc[2][0] += a4.z*b4.x; acc[2][1] += a4.z*b4.y; acc[2][2] += a4.z*b4.z; acc[2][3] += a4.z*b4.w;
            acc[3][0] += a4.w*b4.x; acc[3][1] += a4.w*b4.y; acc[3][2] += a4.w*b4.z; acc[3][3] += a4.w*b4.w;
        }
        __syncthreads();
    }

    #pragma unroll
    for (int i = 0; i < 4; i++) {
        int row = rb + ty*4 + i;
        #pragma unroll
        for (int j = 0; j < 4; j++) {
            int col = cb + tx*4 + j;
            float v = acc[i][j] + bias[col];
            if (act) v = tanhf(v);
            C[(size_t)row*ldc + col] = v;
        }
    }
}

// ---------------- logits GEMM, 64x32 tile, K=256, mask epilogue -------------
__global__ __launch_bounds__(256)
void logits_gemm_kernel(const float* __restrict__ A /*g_hq*/,
                        const float* __restrict__ W /*wq2*/,
                        const float* __restrict__ bias,
                        const float* __restrict__ amask)
{
    __shared__ float as[16][64];
    __shared__ float ws[16][32];
    int tid = threadIdx.x;
    int tx = tid & 7, ty = tid >> 3;       // ty 0..31 (2 rows), tx 0..7 (4 cols)
    int rb = blockIdx.y * 64, cb = blockIdx.x * 32;

    float acc[2][4];
    #pragma unroll
    for (int i = 0; i < 2; i++)
        #pragma unroll
        for (int j = 0; j < 4; j++) acc[i][j] = 0.f;

    int lr = tid >> 2, lk = (tid & 3) * 4;
    int wrw = tid >> 4, wcc = (tid & 15) * 2;

    for (int kb = 0; kb < HPP; kb += 16) {
        float4 av = *(const float4*)(A + (size_t)(rb + lr)*HPP + kb + lk);
        as[lk+0][lr] = av.x; as[lk+1][lr] = av.y;
        as[lk+2][lr] = av.z; as[lk+3][lr] = av.w;
        float2 wv = *(const float2*)(W + (size_t)(kb + wrw)*LL + cb + wcc);
        ws[wrw][wcc] = wv.x; ws[wrw][wcc+1] = wv.y;
        __syncthreads();
        #pragma unroll
        for (int k = 0; k < 16; k++) {
            float2 a2 = *(const float2*)&as[k][ty*2];
            float4 b4 = *(const float4*)&ws[k][tx*4];
            acc[0][0] += a2.x*b4.x; acc[0][1] += a2.x*b4.y;
            acc[0][2] += a2.x*b4.z; acc[0][3] += a2.x*b4.w;
            acc[1][0] += a2.y*b4.x; acc[1][1] += a2.y*b4.y;
            acc[1][2] += a2.y*b4.z; acc[1][3] += a2.y*b4.w;
        }
        __syncthreads();
    }

    #pragma unroll
    for (int i = 0; i < 2; i++) {
        int row = rb + ty*2 + i;
        #pragma unroll
        for (int j = 0; j < 4; j++) {
            int col = cb + tx*4 + j;
            float v  = acc[i][j] + bias[col];
            float mk = amask[(size_t)row*LL + col];
            g_logit[(size_t)row*LL + col] = mk * (-1e6f) + v * (1.f - mk);
        }
    }
}

// ---------------- k-subset relaxation + logprob + adjacency (per sample) ----
__global__ __launch_bounds__(256)
void ksubset_kernel(const float* __restrict__ gum,
                    const float* __restrict__ adjs,
                    float* __restrict__ logp_out, int t)
{
    int n = blockIdx.x, tid = threadIdx.x;
    __shared__ float logit_s[LL];
    __shared__ float score_s[LL];
    __shared__ float sel_s  [LL];
    __shared__ float red_s  [256];

    for (int l = tid; l < LL; l += 256) {
        float a = g_logit[(size_t)n*LL + l];
        logit_s[l] = a;
        score_s[l] = a + gum[((size_t)n*TT + t)*LL + l];
        sel_s[l]   = 0.f;
    }
    __syncthreads();

    for (int it = 0; it < KK; it++) {
        for (int l = tid; l < LL; l += 256) {
            float c = 1.f - sel_s[l];
            c = fminf(fmaxf(c, 1e-6f), 1.f);
            score_s[l] += logf(c);
        }
        __syncthreads();
        float m = -1e30f;
        for (int l = tid; l < LL; l += 256) m = fmaxf(m, score_s[l]);
        m = blk_max256(m, red_s, tid);
        float ps = 0.f;
        for (int l = tid; l < LL; l += 256) ps += expf(score_s[l] - m);
        ps = blk_sum256(ps, red_s, tid);
        float inv = 1.f / ps;
        for (int l = tid; l < LL; l += 256) sel_s[l] += expf(score_s[l] - m) * inv;
        __syncthreads();
    }
    for (int l = tid; l < LL; l += 256) sel_s[l] = fminf(fmaxf(sel_s[l], 0.f), 1.f);
    __syncthreads();

    float m2 = -1e30f;
    for (int l = tid; l < LL; l += 256) m2 = fmaxf(m2, logit_s[l]);
    m2 = blk_max256(m2, red_s, tid);
    float s2 = 0.f;
    for (int l = tid; l < LL; l += 256) s2 += expf(logit_s[l] - m2);
    s2 = blk_sum256(s2, red_s, tid);
    float lse = m2 + logf(s2);
    float lp = 0.f;
    for (int l = tid; l < LL; l += 256) lp += sel_s[l] * (logit_s[l] - lse);
    lp = blk_sum256(lp, red_s, tid);
    if (tid == 0) logp_out[n*TT + t] = lp;

    for (int idx = tid; idx < DD*DD; idx += 256) {
        int i = idx / DD, j = idx % DD;
        float ctrl = 0.f;
        if (i != j) {
            int jj = (j < i) ? j : j - 1;
            ctrl = sel_s[i*(DD-1) + jj];
        }
        g_adj[(size_t)n*DD*DD + idx] = adjs[idx] * (1.f - ctrl);
    }
}

// ---------------- jump: h += tanh((adj@h)@wd + obs*wo + bd) ----------------
__global__ __launch_bounds__(256)
void jump_kernel(const float* __restrict__ wd, const float* __restrict__ bd,
                 const float* __restrict__ wo, const float* __restrict__ edata,
                 int t)
{
    int n = blockIdx.x, tid = threadIdx.x;   // tid = H column
    __shared__ float adj_s[DD*DD];
    __shared__ float ms   [DD*HH];
    __shared__ float obs_s[DD];

    for (int i = tid; i < DD*DD; i += 256) adj_s[i] = g_adj[(size_t)n*DD*DD + i];
    if (tid < DD) obs_s[tid] = edata[((size_t)n*TT + t)*DD + tid];

    float* hn = g_h + (size_t)n * DHH;
    float hcol[DD];
    #pragma unroll
    for (int i = 0; i < DD; i++) hcol[i] = hn[i*HH + tid];
    __syncthreads();

    #pragma unroll
    for (int i = 0; i < DD; i++) {
        float a = 0.f;
        #pragma unroll
        for (int j = 0; j < DD; j++) a += adj_s[i*DD + j] * hcol[j];
        ms[i*HH + tid] = a;
    }
    __syncthreads();

    float acc[DD];
    float wot = wo[tid], bdt = bd[tid];
    #pragma unroll
    for (int i = 0; i < DD; i++) acc[i] = obs_s[i] * wot + bdt;
    for (int k = 0; k < HH; k++) {
        float w = wd[k*HH + tid];
        #pragma unroll
        for (int i = 0; i < DD; i++) acc[i] += ms[i*HH + k] * w;
    }
    #pragma unroll
    for (int i = 0; i < DD; i++) hn[i*HH + tid] = hcol[i] + tanhf(acc[i]);
}

// ---------------- fused ODE integrator + intensity, one block per sample ----
// smem layout (floats): h[8192] | in[8192] | acc[8192] | t1[16384] | w[2*8192]
#define ODE_SMEM_BYTES 229376

__global__ __launch_bounds__(256, 1)
void ode_kernel(const float* __restrict__ wc1, const float* __restrict__ bc1,
                const float* __restrict__ wc2, const float* __restrict__ bc2,
                const float* __restrict__ wi1, const float* __restrict__ bi1,
                const float* __restrict__ wi2, const float* __restrict__ bi2,
                const float* __restrict__ et,  const float* __restrict__ t0v,
                float* __restrict__ out, int t)
{
    extern __shared__ float sm[];
    float* sh_h  = sm;
    float* sh_in = sm + 8192;
    float* sh_ac = sm + 16384;
    float* sh_t1 = sm + 24576;
    float* sh_w  = sm + 40960;     // two 8192-float buffers

    int n = blockIdx.x, tid = threadIdx.x;

    for (int i = tid; i < 8192; i += 256) {
        int r = i >> 8;
        float v = (r < DD) ? g_h[(size_t)n*DHH + i] : 0.f;
        sh_h[i] = v; sh_in[i] = v;
    }
    float tp  = (t == 0) ? t0v[n] : et[n*TT + t - 1];
    float sdt = (et[n*TT + t] - tp) * (1.f / RKN);
    __syncthreads();

    const int rgA = tid >> 6, cgA = tid & 63;   // A: rows 8rgA+, col groups cgA*4 and 256+cgA*4
    const int rgB = tid >> 5, cgB = tid & 31;   // B: rows 4rgB+, col groups cgB*4 and 128+cgB*4

    for (int rk = 0; rk < RKN; rk++)
    for (int s = 0; s < 4; s++) {
        // ===== stage A: t1 = tanh(in @ wc1 + bc1)   (32x256)@(256x512)
        {
            float acc[64];
            #pragma unroll
            for (int q = 0; q < 64; q++) acc[q] = 0.f;
            cp_tile(sh_w, wc1, 2048, tid);
            for (int kb = 0; kb < 16; kb++) {
                if (kb + 1 < 16)
                    cp_tile(sh_w + ((kb+1)&1)*8192, wc1 + (kb+1)*16*HCC, 2048, tid);
                if (kb + 1 < 16) __pipeline_wait_prior(1); else __pipeline_wait_prior(0);
                __syncthreads();
                const float* wb  = sh_w + (kb&1)*8192;
                const float* inb = sh_in + kb*16;
                #pragma unroll 4
                for (int k = 0; k < 16; k++) {
                    // conflict-free: warp lanes read 16B-contiguous chunks
                    float4 w0 = *(const float4*)&wb[k*HCC + cgA*4];
                    float4 w1 = *(const float4*)&wb[k*HCC + 256 + cgA*4];
                    #pragma unroll
                    for (int i = 0; i < 8; i++) {
                        float a = inb[(rgA*8 + i)*HH + k];
                        FMA8(a, w0, w1, acc, i*8);
                    }
                }
                __syncthreads();
            }
            #pragma unroll
            for (int j = 0; j < 4; j++) {
                float b0 = bc1[cgA*4 + j];
                float b1 = bc1[256 + cgA*4 + j];
                #pragma unroll
                for (int i = 0; i < 8; i++) {
                    sh_t1[(rgA*8 + i)*HCC + cgA*4 + j]       = tanhf(acc[i*8 + j]     + b0);
                    sh_t1[(rgA*8 + i)*HCC + 256 + cgA*4 + j] = tanhf(acc[i*8 + 4 + j] + b1);
                }
            }
            __syncthreads();
        }
        // ===== stage B: kv = t1 @ wc2 + bc2   (32x512)@(512x256), RK epilogue
        {
            float acc[32];
            #pragma unroll
            for (int q = 0; q < 32; q++) acc[q] = 0.f;
            cp_tile(sh_w, wc2, 1024, tid);
            for (int kb = 0; kb < 32; kb++) {
                if (kb + 1 < 32)
                    cp_tile(sh_w + ((kb+1)&1)*8192, wc2 + (kb+1)*16*HH, 1024, tid);
                if (kb + 1 < 32) __pipeline_wait_prior(1); else __pipeline_wait_prior(0);
                __syncthreads();
                const float* wb = sh_w + (kb&1)*8192;
                const float* tb = sh_t1 + kb*16;
                #pragma unroll 4
                for (int k = 0; k < 16; k++) {
                    float4 w0 = *(const float4*)&wb[k*HH + cgB*4];
                    float4 w1 = *(const float4*)&wb[k*HH + 128 + cgB*4];
                    #pragma unroll
                    for (int i = 0; i < 4; i++) {
                        float a = tb[(rgB*4 + i)*HCC + k];
                        FMA8(a, w0, w1, acc, i*8);
                    }
                }
                __syncthreads();
            }
            #pragma unroll
            for (int i = 0; i < 4; i++) {
                int r = rgB*4 + i;
                #pragma unroll
                for (int jj = 0; jj < 8; jj++) {
                    int c = (jj < 4) ? (cgB*4 + jj) : (128 + cgB*4 + (jj - 4));
                    float kv = acc[i*8 + jj] + bc2[c];
                    int idx = r*HH + c;
                    if (s == 0)      { sh_ac[idx] = kv;        sh_in[idx] = sh_h[idx] + 0.5f*sdt*kv; }
                    else if (s == 1) { sh_ac[idx] += 2.f*kv;   sh_in[idx] = sh_h[idx] + 0.5f*sdt*kv; }
                    else if (s == 2) { sh_ac[idx] += 2.f*kv;   sh_in[idx] = sh_h[idx] + sdt*kv; }
                    else             { float hn = sh_h[idx] + (sdt*(1.f/6.f))*(sh_ac[idx] + kv);
                                       sh_h[idx] = hn; sh_in[idx] = hn; }
                }
            }
            __syncthreads();
        }
    }

    // write back h
    for (int i = tid; i < DHH; i += 256) g_h[(size_t)n*DHH + i] = sh_h[i];

    // ===== intensity: softplus( tanh(h@wi1+bi1) @ wi2 + bi2 )
    {
        float acc[16];
        #pragma unroll
        for (int q = 0; q < 16; q++) acc[q] = 0.f;
        const int rgI = tid >> 5, cgI = tid & 31;   // rows 4rgI+, cols 4cgI+
        cp_tile(sh_w, wi1, 512, tid);
        for (int kb = 0; kb < 16; kb++) {
            if (kb + 1 < 16)
                cp_tile(sh_w + ((kb+1)&1)*8192, wi1 + (kb+1)*16*HII, 512, tid);
            if (kb + 1 < 16) __pipeline_wait_prior(1); else __pipeline_wait_prior(0);
            __syncthreads();
            const float* wb = sh_w + (kb&1)*8192;
            #pragma unroll 4
            for (int k = 0; k < 16; k++) {
                float4 w = *(const float4*)&wb[k*HII + cgI*4];
                #pragma unroll
                for (int i = 0; i < 4; i++) {
                    float a = sh_h[(rgI*4 + i)*HH + kb*16 + k];
                    acc[i*4+0] = fmaf(a, w.x, acc[i*4+0]);
                    acc[i*4+1] = fmaf(a, w.y, acc[i*4+1]);
                    acc[i*4+2] = fmaf(a, w.z, acc[i*4+2]);
                    acc[i*4+3] = fmaf(a, w.w, acc[i*4+3]);
                }
            }
            __syncthreads();
        }
        #pragma unroll
        for (int j = 0; j < 4; j++) {
            int c = cgI*4 + j;
            float b = bi1[c], wv = wi2[c];
            #pragma unroll
            for (int i = 0; i < 4; i++)
                sh_t1[(rgI*4 + i)*HII + c] = tanhf(acc[i*4 + j] + b) * wv;
        }
        __syncthreads();
        if (tid < DD) {
            float ssum = 0.f;
            for (int j = 0; j < HII; j++) ssum += sh_t1[tid*HII + j];
            float x = ssum + bi2[0];
            float sp = fmaxf(x, 0.f) + log1pf(expf(-fabsf(x)));
            out[((size_t)n*TT + t)*DD + tid] = sp;
        }
    }
}

// ---------------- launch ----------------
extern "C" void kernel_launch(void* const* d_in, const int* in_sizes, int n_in,
                              void* d_out, int out_size)
{
    const float* event_time = (const float*)d_in[0];
    const float* event_data = (const float*)d_in[1];
    const float* t0     = (const float*)d_in[2];
    const float* amask  = (const float*)d_in[3];
    const float* gum    = (const float*)d_in[4];
    const float* init_h = (const float*)d_in[5];
    const float* adjs   = (const float*)d_in[6];
    const float* wc1 = (const float*)d_in[7];  const float* bc1 = (const float*)d_in[8];
    const float* wc2 = (const float*)d_in[9];  const float* bc2 = (const float*)d_in[10];
    const float* wd  = (const float*)d_in[11]; const float* bd  = (const float*)d_in[12];
    const float* wo  = (const float*)d_in[13];
    const float* wi1 = (const float*)d_in[14]; const float* bi1 = (const float*)d_in[15];
    const float* wi2 = (const float*)d_in[16]; const float* bi2 = (const float*)d_in[17];
    const float* wr  = (const float*)d_in[18]; const float* br  = (const float*)d_in[19];
    const float* wp  = (const float*)d_in[20]; const float* bp  = (const float*)d_in[21];
    const float* wm  = (const float*)d_in[22]; const float* bm  = (const float*)d_in[23];
    const float* wq1 = (const float*)d_in[24]; const float* bq1 = (const float*)d_in[25];
    const float* wq2 = (const float*)d_in[26]; const float* bq2 = (const float*)d_in[27];

    float* out      = (float*)d_out;
    float* out_logp = out + (size_t)NN*TT*DD;

    void* p;
    cudaGetSymbolAddress(&p, g_e);     float* e_ptr   = (float*)p;
    cudaGetSymbolAddress(&p, g_cat);   float* cat_ptr = (float*)p;
    cudaGetSymbolAddress(&p, g_hq);    float* hq_ptr  = (float*)p;

    cudaFuncSetAttribute(ode_kernel, cudaFuncAttributeMaxDynamicSharedMemorySize,
                         ODE_SMEM_BYTES);

    init_h_kernel<<<(NN*DHH + 255)/256, 256>>>(init_h);

    for (int t = 0; t < TT; t++) {
        // policy: batched GEMM chain + k-subset
        e_gemm_kernel<<<dim3(2, 2, P1KS), 256>>>(wr);
        e_reduce_kernel<<<(NN*EE)/256, 256>>>(br);
        gemm64_kernel<<<dim3(2, 2), 256>>>(e_ptr, EE, wp, EE, bp,
                                           cat_ptr, 2*EE, EE, 0);          // pos
        gemm64_kernel<<<dim3(2, 2), 256>>>(e_ptr, EE, wm, EE, bm,
                                           cat_ptr + EE, 2*EE, EE, 0);     // mage
        gemm64_kernel<<<dim3(4, 2), 256>>>(cat_ptr, 2*EE, wq1, HPP, bq1,
                                           hq_ptr, HPP, 2*EE, 1);          // hq (tanh)
        logits_gemm_kernel<<<dim3(LL/32, 2), 256>>>(hq_ptr, wq2, bq2, amask);
        ksubset_kernel<<<NN, 256>>>(gum, adjs, out_logp, t);
        // jump + ODE + intensity
        jump_kernel<<<NN, 256>>>(wd, bd, wo, event_data, t);
        ode_kernel<<<NN, 256, ODE_SMEM_BYTES>>>(wc1, bc1, wc2, bc2,
                                                wi1, bi1, wi2, bi2,
                                                event_time, t0, out, t);
    }
}

// round 5
// speedup vs baseline: 1.3374x; 1.0161x over previous
#include <cuda_runtime.h>
#include <cuda_pipeline.h>
#include <math.h>

// ---------------- problem dims ----------------
#define NN   128
#define TT   16
#define DD   25
#define HH   256
#define HCC  512
#define HII  128
#define EE   128
#define HPP  256
#define LL   608          // D*(D-1)+8
#define KK   8
#define RKN  2
#define DHH  (DD*HH)      // 6400
#define P1KS 32           // split-K factor for e-GEMM
#define P1KC 200          // 6400/32

typedef unsigned long long u64;

// packed fp32x2 helpers (Blackwell native FFMA2 — bit-identical to 2x FFMA)
__device__ __forceinline__ u64 pk2(float x) {
    u64 r; asm("mov.b64 %0, {%1, %1};" : "=l"(r) : "f"(x)); return r;
}
__device__ __forceinline__ void fma2(u64& d, u64 a, u64 b) {
    asm("fma.rn.f32x2 %0, %1, %2, %0;" : "+l"(d) : "l"(a), "l"(b));
}
__device__ __forceinline__ float2 up2(u64 p) {
    float2 v; asm("mov.b64 {%0, %1}, %2;" : "=f"(v.x), "=f"(v.y) : "l"(p)); return v;
}

// ---------------- persistent device scratch ----------------
__device__ float g_h     [NN*DHH];         // state h (N,D,H)
__device__ float g_adj   [NN*DD*DD];       // per-sample controlled adjacency
__device__ float g_epart [P1KS*NN*EE];     // split-K partials for e
__device__ float g_e     [NN*EE];          // e = tanh(hflat @ wr + br)
__device__ float g_cat   [NN*2*EE];        // [pos | mage] (128 x 256)
__device__ float g_hq    [NN*HPP];         // tanh policy hidden (128 x 256)
__device__ float g_logit [NN*LL];          // masked logits (128 x 608)

// ---------------- helpers ----------------
__device__ __forceinline__ void cp_tile(float* dst, const float* src, int nf4, int tid) {
    const float4* s4 = (const float4*)src;
    float4* d4 = (float4*)dst;
    for (int p = tid; p < nf4; p += 256)
        __pipeline_memcpy_async(&d4[p], &s4[p], 16);
    __pipeline_commit();
}

__device__ __forceinline__ float blk_max256(float v, float* red, int tid) {
    red[tid] = v; __syncthreads();
    #pragma unroll
    for (int s = 128; s > 0; s >>= 1) {
        if (tid < s) red[tid] = fmaxf(red[tid], red[tid + s]);
        __syncthreads();
    }
    v = red[0]; __syncthreads();
    return v;
}
__device__ __forceinline__ float blk_sum256(float v, float* red, int tid) {
    red[tid] = v; __syncthreads();
    #pragma unroll
    for (int s = 128; s > 0; s >>= 1) {
        if (tid < s) red[tid] += red[tid + s];
        __syncthreads();
    }
    v = red[0]; __syncthreads();
    return v;
}

// ---------------- init h = broadcast(init_hstate) ----------------
__global__ void init_h_kernel(const float* __restrict__ ih) {
    int idx = blockIdx.x * blockDim.x + threadIdx.x;
    if (idx < NN*DHH) g_h[idx] = ih[idx % DHH];
}

// ---------------- P1: e partials, split-K GEMM  (128x6400 @ 6400x128) ------
__global__ __launch_bounds__(256)
void e_gemm_kernel(const float* __restrict__ wr)
{
    __shared__ float sa[8][64];
    __shared__ float sb[8][64];
    int tid = threadIdx.x;
    int tx = tid & 15, ty = tid >> 4;
    int rb = blockIdx.y * 64, cb = blockIdx.x * 64;
    int k0 = blockIdx.z * P1KC;

    float acc[4][4];
    #pragma unroll
    for (int i = 0; i < 4; i++)
        #pragma unroll
        for (int j = 0; j < 4; j++) acc[i][j] = 0.f;

    int r  = tid >> 2, kk  = (tid & 3) * 2;
    int k2 = tid >> 5, c2  = (tid & 31) * 2;

    for (int kb = 0; kb < P1KC; kb += 8) {
        float2 av = *(const float2*)&g_h[(size_t)(rb + r)*DHH + k0 + kb + kk];
        sa[kk][r] = av.x; sa[kk+1][r] = av.y;
        float2 wv = *(const float2*)&wr[(size_t)(k0 + kb + k2)*EE + cb + c2];
        sb[k2][c2] = wv.x; sb[k2][c2+1] = wv.y;
        __syncthreads();
        #pragma unroll
        for (int k = 0; k < 8; k++) {
            float4 a4 = *(const float4*)&sa[k][ty*4];
            float4 b4 = *(const float4*)&sb[k][tx*4];
            acc[0][0] += a4.x*b4.x; acc[0][1] += a4.x*b4.y; acc[0][2] += a4.x*b4.z; acc[0][3] += a4.x*b4.w;
            acc[1][0] += a4.y*b4.x; acc[1][1] += a4.y*b4.y; acc[1][2] += a4.y*b4.z; acc[1][3] += a4.y*b4.w;
            acc[2][0] += a4.z*b4.x; acc[2][1] += a4.z*b4.y; acc[2][2] += a4.z*b4.z; acc[2][3] += a4.z*b4.w;
            acc[3][0] += a4.w*b4.x; acc[3][1] += a4.w*b4.y; acc[3][2] += a4.w*b4.z; acc[3][3] += a4.w*b4.w;
        }
        __syncthreads();
    }
    float* dst = g_epart + (size_t)blockIdx.z * (NN*EE);
    #pragma unroll
    for (int i = 0; i < 4; i++)
        #pragma unroll
        for (int j = 0; j < 4; j++)
            dst[(rb + ty*4 + i)*EE + cb + tx*4 + j] = acc[i][j];
}

// ---------------- P1r: reduce partials + tanh(+br) ----------------
__global__ __launch_bounds__(256)
void e_reduce_kernel(const float* __restrict__ br)
{
    int i = blockIdx.x * 256 + threadIdx.x;     // 16384 total
    float s = 0.f;
    #pragma unroll
    for (int k = 0; k < P1KS; k++) s += g_epart[(size_t)k*(NN*EE) + i];
    g_e[i] = tanhf(s + br[i & (EE-1)]);
}

// ---------------- small batched GEMM, 64x64 tile, K param, optional tanh ----
__global__ __launch_bounds__(256)
void gemm64_kernel(const float* __restrict__ A, int lda,
                   const float* __restrict__ W, int ldw,
                   const float* __restrict__ bias,
                   float* __restrict__ C, int ldc,
                   int Kd, int act)
{
    __shared__ float as[16][64];
    __shared__ float ws[16][64];
    int tid = threadIdx.x;
    int tx = tid & 15, ty = tid >> 4;
    int rb = blockIdx.y * 64, cb = blockIdx.x * 64;

    float acc[4][4];
    #pragma unroll
    for (int i = 0; i < 4; i++)
        #pragma unroll
        for (int j = 0; j < 4; j++) acc[i][j] = 0.f;

    int lr = tid >> 2, lk = (tid & 3) * 4;
    int wrw = tid >> 4, wcc = (tid & 15) * 4;

    for (int kb = 0; kb < Kd; kb += 16) {
        float4 av = *(const float4*)(A + (size_t)(rb + lr)*lda + kb + lk);
        as[lk+0][lr] = av.x; as[lk+1][lr] = av.y;
        as[lk+2][lr] = av.z; as[lk+3][lr] = av.w;
        *(float4*)&ws[wrw][wcc] = *(const float4*)(W + (size_t)(kb + wrw)*ldw + cb + wcc);
        __syncthreads();
        #pragma unroll
        for (int k = 0; k < 16; k++) {
            float4 a4 = *(const float4*)&as[k][ty*4];
            float4 b4 = *(const float4*)&ws[k][tx*4];
            acc[0][0] += a4.x*b4.x; acc[0][1] += a4.x*b4.y; acc[0][2] += a4.x*b4.z; acc[0][3] += a4.x*b4.w;
            acc[1][0] += a4.y*b4.x; acc[1][1] += a4.y*b4.y; acc[1][2] += a4.y*b4.z; acc[1][3] += a4.y*b4.w;
            acc[2][0] += a4.z*b4.x; acc[2][1] += a4.z*b4.y; acc[2][2] += a4.z*b4.z; acc[2][3] += a4.z*b4.w;
            acc[3][0] += a4.w*b4.x; acc[3][1] += a4.w*b4.y; acc[3][2] += a4.w*b4.z; acc[3][3] += a4.w*b4.w;
        }
        __syncthreads();
    }

    #pragma unroll
    for (int i = 0; i < 4; i++) {
        int row = rb + ty*4 + i;
        #pragma unroll
        for (int j = 0; j < 4; j++) {
            int col = cb + tx*4 + j;
            float v = acc[i][j] + bias[col];
            if (act) v = tanhf(v);
            C[(size_t)row*ldc + col] = v;
        }
    }
}

// ---------------- logits GEMM, 64x32 tile, K=256, mask epilogue -------------
__global__ __launch_bounds__(256)
void logits_gemm_kernel(const float* __restrict__ A /*g_hq*/,
                        const float* __restrict__ W /*wq2*/,
                        const float* __restrict__ bias,
                        const float* __restrict__ amask)
{
    __shared__ float as[16][64];
    __shared__ float ws[16][32];
    int tid = threadIdx.x;
    int tx = tid & 7, ty = tid >> 3;
    int rb = blockIdx.y * 64, cb = blockIdx.x * 32;

    float acc[2][4];
    #pragma unroll
    for (int i = 0; i < 2; i++)
        #pragma unroll
        for (int j = 0; j < 4; j++) acc[i][j] = 0.f;

    int lr = tid >> 2, lk = (tid & 3) * 4;
    int wrw = tid >> 4, wcc = (tid & 15) * 2;

    for (int kb = 0; kb < HPP; kb += 16) {
        float4 av = *(const float4*)(A + (size_t)(rb + lr)*HPP + kb + lk);
        as[lk+0][lr] = av.x; as[lk+1][lr] = av.y;
        as[lk+2][lr] = av.z; as[lk+3][lr] = av.w;
        float2 wv = *(const float2*)(W + (size_t)(kb + wrw)*LL + cb + wcc);
        ws[wrw][wcc] = wv.x; ws[wrw][wcc+1] = wv.y;
        __syncthreads();
        #pragma unroll
        for (int k = 0; k < 16; k++) {
            float2 a2 = *(const float2*)&as[k][ty*2];
            float4 b4 = *(const float4*)&ws[k][tx*4];
            acc[0][0] += a2.x*b4.x; acc[0][1] += a2.x*b4.y;
            acc[0][2] += a2.x*b4.z; acc[0][3] += a2.x*b4.w;
            acc[1][0] += a2.y*b4.x; acc[1][1] += a2.y*b4.y;
            acc[1][2] += a2.y*b4.z; acc[1][3] += a2.y*b4.w;
        }
        __syncthreads();
    }

    #pragma unroll
    for (int i = 0; i < 2; i++) {
        int row = rb + ty*2 + i;
        #pragma unroll
        for (int j = 0; j < 4; j++) {
            int col = cb + tx*4 + j;
            float v  = acc[i][j] + bias[col];
            float mk = amask[(size_t)row*LL + col];
            g_logit[(size_t)row*LL + col] = mk * (-1e6f) + v * (1.f - mk);
        }
    }
}

// ---------------- k-subset relaxation + logprob + adjacency (per sample) ----
__global__ __launch_bounds__(256)
void ksubset_kernel(const float* __restrict__ gum,
                    const float* __restrict__ adjs,
                    float* __restrict__ logp_out, int t)
{
    int n = blockIdx.x, tid = threadIdx.x;
    __shared__ float logit_s[LL];
    __shared__ float score_s[LL];
    __shared__ float sel_s  [LL];
    __shared__ float red_s  [256];

    for (int l = tid; l < LL; l += 256) {
        float a = g_logit[(size_t)n*LL + l];
        logit_s[l] = a;
        score_s[l] = a + gum[((size_t)n*TT + t)*LL + l];
        sel_s[l]   = 0.f;
    }
    __syncthreads();

    for (int it = 0; it < KK; it++) {
        for (int l = tid; l < LL; l += 256) {
            float c = 1.f - sel_s[l];
            c = fminf(fmaxf(c, 1e-6f), 1.f);
            score_s[l] += logf(c);
        }
        __syncthreads();
        float m = -1e30f;
        for (int l = tid; l < LL; l += 256) m = fmaxf(m, score_s[l]);
        m = blk_max256(m, red_s, tid);
        float ps = 0.f;
        for (int l = tid; l < LL; l += 256) ps += expf(score_s[l] - m);
        ps = blk_sum256(ps, red_s, tid);
        float inv = 1.f / ps;
        for (int l = tid; l < LL; l += 256) sel_s[l] += expf(score_s[l] - m) * inv;
        __syncthreads();
    }
    for (int l = tid; l < LL; l += 256) sel_s[l] = fminf(fmaxf(sel_s[l], 0.f), 1.f);
    __syncthreads();

    float m2 = -1e30f;
    for (int l = tid; l < LL; l += 256) m2 = fmaxf(m2, logit_s[l]);
    m2 = blk_max256(m2, red_s, tid);
    float s2 = 0.f;
    for (int l = tid; l < LL; l += 256) s2 += expf(logit_s[l] - m2);
    s2 = blk_sum256(s2, red_s, tid);
    float lse = m2 + logf(s2);
    float lp = 0.f;
    for (int l = tid; l < LL; l += 256) lp += sel_s[l] * (logit_s[l] - lse);
    lp = blk_sum256(lp, red_s, tid);
    if (tid == 0) logp_out[n*TT + t] = lp;

    for (int idx = tid; idx < DD*DD; idx += 256) {
        int i = idx / DD, j = idx % DD;
        float ctrl = 0.f;
        if (i != j) {
            int jj = (j < i) ? j : j - 1;
            ctrl = sel_s[i*(DD-1) + jj];
        }
        g_adj[(size_t)n*DD*DD + idx] = adjs[idx] * (1.f - ctrl);
    }
}

// ---------------- jump: h += tanh((adj@h)@wd + obs*wo + bd) ----------------
__global__ __launch_bounds__(256)
void jump_kernel(const float* __restrict__ wd, const float* __restrict__ bd,
                 const float* __restrict__ wo, const float* __restrict__ edata,
                 int t)
{
    int n = blockIdx.x, tid = threadIdx.x;   // tid = H column
    __shared__ float adj_s[DD*DD];
    __shared__ float ms   [DD*HH];
    __shared__ float obs_s[DD];

    for (int i = tid; i < DD*DD; i += 256) adj_s[i] = g_adj[(size_t)n*DD*DD + i];
    if (tid < DD) obs_s[tid] = edata[((size_t)n*TT + t)*DD + tid];

    float* hn = g_h + (size_t)n * DHH;
    float hcol[DD];
    #pragma unroll
    for (int i = 0; i < DD; i++) hcol[i] = hn[i*HH + tid];
    __syncthreads();

    #pragma unroll
    for (int i = 0; i < DD; i++) {
        float a = 0.f;
        #pragma unroll
        for (int j = 0; j < DD; j++) a += adj_s[i*DD + j] * hcol[j];
        ms[i*HH + tid] = a;
    }
    __syncthreads();

    float acc[DD];
    float wot = wo[tid], bdt = bd[tid];
    #pragma unroll
    for (int i = 0; i < DD; i++) acc[i] = obs_s[i] * wot + bdt;
    for (int k = 0; k < HH; k++) {
        float w = wd[k*HH + tid];
        #pragma unroll
        for (int i = 0; i < DD; i++) acc[i] += ms[i*HH + k] * w;
    }
    #pragma unroll
    for (int i = 0; i < DD; i++) hn[i*HH + tid] = hcol[i] + tanhf(acc[i]);
}

// ---------------- fused ODE integrator + intensity, one block per sample ----
// smem layout (floats): h[8192] | in[8192] | acc[8192] | t1[16384] | w[2*8192]
#define ODE_SMEM_BYTES 229376

__global__ __launch_bounds__(256, 1)
void ode_kernel(const float* __restrict__ wc1, const float* __restrict__ bc1,
                const float* __restrict__ wc2, const float* __restrict__ bc2,
                const float* __restrict__ wi1, const float* __restrict__ bi1,
                const float* __restrict__ wi2, const float* __restrict__ bi2,
                const float* __restrict__ et,  const float* __restrict__ t0v,
                float* __restrict__ out, int t)
{
    extern __shared__ float sm[];
    float* sh_h  = sm;
    float* sh_in = sm + 8192;
    float* sh_ac = sm + 16384;
    float* sh_t1 = sm + 24576;
    float* sh_w  = sm + 40960;     // two 8192-float buffers

    int n = blockIdx.x, tid = threadIdx.x;

    for (int i = tid; i < 8192; i += 256) {
        int r = i >> 8;
        float v = (r < DD) ? g_h[(size_t)n*DHH + i] : 0.f;
        sh_h[i] = v; sh_in[i] = v;
    }
    float tp  = (t == 0) ? t0v[n] : et[n*TT + t - 1];
    float sdt = (et[n*TT + t] - tp) * (1.f / RKN);
    __syncthreads();

    const int rgA = tid >> 6, cgA = tid & 63;   // A: rows 8rgA+, col groups cgA*4 and 256+cgA*4
    const int rgB = tid >> 5, cgB = tid & 31;   // B: rows 4rgB+, col groups cgB*4 and 128+cgB*4

    for (int rk = 0; rk < RKN; rk++)
    for (int s = 0; s < 4; s++) {
        // ===== stage A: t1 = tanh(in @ wc1 + bc1)   (32x256)@(256x512)
        {
            u64 acc2[32];                       // 8 rows x 4 col-pairs
            #pragma unroll
            for (int q = 0; q < 32; q++) acc2[q] = 0ull;
            cp_tile(sh_w, wc1, 2048, tid);
            for (int kb = 0; kb < 16; kb++) {
                if (kb + 1 < 16)
                    cp_tile(sh_w + ((kb+1)&1)*8192, wc1 + (kb+1)*16*HCC, 2048, tid);
                if (kb + 1 < 16) __pipeline_wait_prior(1); else __pipeline_wait_prior(0);
                __syncthreads();
                const float* wb  = sh_w + (kb&1)*8192;
                const float* inb = sh_in + kb*16;
                #pragma unroll 4
                for (int k = 0; k < 16; k++) {
                    ulonglong2 w0 = *(const ulonglong2*)&wb[k*HCC + cgA*4];
                    ulonglong2 w1 = *(const ulonglong2*)&wb[k*HCC + 256 + cgA*4];
                    #pragma unroll
                    for (int i = 0; i < 8; i++) {
                        u64 aa = pk2(inb[(rgA*8 + i)*HH + k]);
                        fma2(acc2[i*4+0], aa, w0.x);
                        fma2(acc2[i*4+1], aa, w0.y);
                        fma2(acc2[i*4+2], aa, w1.x);
                        fma2(acc2[i*4+3], aa, w1.y);
                    }
                }
                __syncthreads();
            }
            #pragma unroll
            for (int p = 0; p < 2; p++) {
                int c = p*256 + cgA*4;
                float b0 = bc1[c], b1 = bc1[c+1], b2 = bc1[c+2], b3 = bc1[c+3];
                #pragma unroll
                for (int i = 0; i < 8; i++) {
                    float2 v0 = up2(acc2[i*4 + p*2 + 0]);
                    float2 v1 = up2(acc2[i*4 + p*2 + 1]);
                    float* dst = &sh_t1[(rgA*8 + i)*HCC + c];
                    dst[0] = tanhf(v0.x + b0);
                    dst[1] = tanhf(v0.y + b1);
                    dst[2] = tanhf(v1.x + b2);
                    dst[3] = tanhf(v1.y + b3);
                }
            }
            __syncthreads();
        }
        // ===== stage B: kv = t1 @ wc2 + bc2   (32x512)@(512x256), RK epilogue
        {
            u64 acc2[16];                       // 4 rows x 4 col-pairs
            #pragma unroll
            for (int q = 0; q < 16; q++) acc2[q] = 0ull;
            cp_tile(sh_w, wc2, 1024, tid);
            for (int kb = 0; kb < 32; kb++) {
                if (kb + 1 < 32)
                    cp_tile(sh_w + ((kb+1)&1)*8192, wc2 + (kb+1)*16*HH, 1024, tid);
                if (kb + 1 < 32) __pipeline_wait_prior(1); else __pipeline_wait_prior(0);
                __syncthreads();
                const float* wb = sh_w + (kb&1)*8192;
                const float* tb = sh_t1 + kb*16;
                #pragma unroll 4
                for (int k = 0; k < 16; k++) {
                    ulonglong2 w0 = *(const ulonglong2*)&wb[k*HH + cgB*4];
                    ulonglong2 w1 = *(const ulonglong2*)&wb[k*HH + 128 + cgB*4];
                    #pragma unroll
                    for (int i = 0; i < 4; i++) {
                        u64 aa = pk2(tb[(rgB*4 + i)*HCC + k]);
                        fma2(acc2[i*4+0], aa, w0.x);
                        fma2(acc2[i*4+1], aa, w0.y);
                        fma2(acc2[i*4+2], aa, w1.x);
                        fma2(acc2[i*4+3], aa, w1.y);
                    }
                }
                __syncthreads();
            }
            #pragma unroll
            for (int i = 0; i < 4; i++) {
                int r = rgB*4 + i;
                #pragma unroll
                for (int p = 0; p < 2; p++) {
                    int c = p*128 + cgB*4;
                    float2 v0 = up2(acc2[i*4 + p*2 + 0]);
                    float2 v1 = up2(acc2[i*4 + p*2 + 1]);
                    float kvv[4] = { v0.x + bc2[c], v0.y + bc2[c+1],
                                     v1.x + bc2[c+2], v1.y + bc2[c+3] };
                    #pragma unroll
                    for (int j = 0; j < 4; j++) {
                        float kv = kvv[j];
                        int idx = r*HH + c + j;
                        if (s == 0)      { sh_ac[idx] = kv;        sh_in[idx] = sh_h[idx] + 0.5f*sdt*kv; }
                        else if (s == 1) { sh_ac[idx] += 2.f*kv;   sh_in[idx] = sh_h[idx] + 0.5f*sdt*kv; }
                        else if (s == 2) { sh_ac[idx] += 2.f*kv;   sh_in[idx] = sh_h[idx] + sdt*kv; }
                        else             { float hn = sh_h[idx] + (sdt*(1.f/6.f))*(sh_ac[idx] + kv);
                                           sh_h[idx] = hn; sh_in[idx] = hn; }
                    }
                }
            }
            __syncthreads();
        }
    }

    // write back h
    for (int i = tid; i < DHH; i += 256) g_h[(size_t)n*DHH + i] = sh_h[i];

    // ===== intensity: softplus( tanh(h@wi1+bi1) @ wi2 + bi2 )
    {
        u64 acc2[8];                            // 4 rows x 2 col-pairs
        #pragma unroll
        for (int q = 0; q < 8; q++) acc2[q] = 0ull;
        const int rgI = tid >> 5, cgI = tid & 31;   // rows 4rgI+, cols 4cgI+
        cp_tile(sh_w, wi1, 512, tid);
        for (int kb = 0; kb < 16; kb++) {
            if (kb + 1 < 16)
                cp_tile(sh_w + ((kb+1)&1)*8192, wi1 + (kb+1)*16*HII, 512, tid);
            if (kb + 1 < 16) __pipeline_wait_prior(1); else __pipeline_wait_prior(0);
            __syncthreads();
            const float* wb = sh_w + (kb&1)*8192;
            #pragma unroll 4
            for (int k = 0; k < 16; k++) {
                ulonglong2 w = *(const ulonglong2*)&wb[k*HII + cgI*4];
                #pragma unroll
                for (int i = 0; i < 4; i++) {
                    u64 aa = pk2(sh_h[(rgI*4 + i)*HH + kb*16 + k]);
                    fma2(acc2[i*2+0], aa, w.x);
                    fma2(acc2[i*2+1], aa, w.y);
                }
            }
            __syncthreads();
        }
        {
            int c = cgI*4;
            float b0 = bi1[c], b1 = bi1[c+1], b2 = bi1[c+2], b3 = bi1[c+3];
            float q0 = wi2[c], q1 = wi2[c+1], q2 = wi2[c+2], q3 = wi2[c+3];
            #pragma unroll
            for (int i = 0; i < 4; i++) {
                float2 v0 = up2(acc2[i*2+0]);
                float2 v1 = up2(acc2[i*2+1]);
                float* dst = &sh_t1[(rgI*4 + i)*HII + c];
                dst[0] = tanhf(v0.x + b0) * q0;
                dst[1] = tanhf(v0.y + b1) * q1;
                dst[2] = tanhf(v1.x + b2) * q2;
                dst[3] = tanhf(v1.y + b3) * q3;
            }
        }
        __syncthreads();
        if (tid < DD) {
            float ssum = 0.f;
            for (int j = 0; j < HII; j++) ssum += sh_t1[tid*HII + j];
            float x = ssum + bi2[0];
            float sp = fmaxf(x, 0.f) + log1pf(expf(-fabsf(x)));
            out[((size_t)n*TT + t)*DD + tid] = sp;
        }
    }
}

// ---------------- launch ----------------
extern "C" void kernel_launch(void* const* d_in, const int* in_sizes, int n_in,
                              void* d_out, int out_size)
{
    const float* event_time = (const float*)d_in[0];
    const float* event_data = (const float*)d_in[1];
    const float* t0     = (const float*)d_in[2];
    const float* amask  = (const float*)d_in[3];
    const float* gum    = (const float*)d_in[4];
    const float* init_h = (const float*)d_in[5];
    const float* adjs   = (const float*)d_in[6];
    const float* wc1 = (const float*)d_in[7];  const float* bc1 = (const float*)d_in[8];
    const float* wc2 = (const float*)d_in[9];  const float* bc2 = (const float*)d_in[10];
    const float* wd  = (const float*)d_in[11]; const float* bd  = (const float*)d_in[12];
    const float* wo  = (const float*)d_in[13];
    const float* wi1 = (const float*)d_in[14]; const float* bi1 = (const float*)d_in[15];
    const float* wi2 = (const float*)d_in[16]; const float* bi2 = (const float*)d_in[17];
    const float* wr  = (const float*)d_in[18]; const float* br  = (const float*)d_in[19];
    const float* wp  = (const float*)d_in[20]; const float* bp  = (const float*)d_in[21];
    const float* wm  = (const float*)d_in[22]; const float* bm  = (const float*)d_in[23];
    const float* wq1 = (const float*)d_in[24]; const float* bq1 = (const float*)d_in[25];
    const float* wq2 = (const float*)d_in[26]; const float* bq2 = (const float*)d_in[27];

    float* out      = (float*)d_out;
    float* out_logp = out + (size_t)NN*TT*DD;

    void* p;
    cudaGetSymbolAddress(&p, g_e);     float* e_ptr   = (float*)p;
    cudaGetSymbolAddress(&p, g_cat);   float* cat_ptr = (float*)p;
    cudaGetSymbolAddress(&p, g_hq);    float* hq_ptr  = (float*)p;

    cudaFuncSetAttribute(ode_kernel, cudaFuncAttributeMaxDynamicSharedMemorySize,
                         ODE_SMEM_BYTES);

    init_h_kernel<<<(NN*DHH + 255)/256, 256>>>(init_h);

    for (int t = 0; t < TT; t++) {
        // policy: batched GEMM chain + k-subset
        e_gemm_kernel<<<dim3(2, 2, P1KS), 256>>>(wr);
        e_reduce_kernel<<<(NN*EE)/256, 256>>>(br);
        gemm64_kernel<<<dim3(2, 2), 256>>>(e_ptr, EE, wp, EE, bp,
                                           cat_ptr, 2*EE, EE, 0);          // pos
        gemm64_kernel<<<dim3(2, 2), 256>>>(e_ptr, EE, wm, EE, bm,
                                           cat_ptr + EE, 2*EE, EE, 0);     // mage
        gemm64_kernel<<<dim3(4, 2), 256>>>(cat_ptr, 2*EE, wq1, HPP, bq1,
                                           hq_ptr, HPP, 2*EE, 1);          // hq (tanh)
        logits_gemm_kernel<<<dim3(LL/32, 2), 256>>>(hq_ptr, wq2, bq2, amask);
        ksubset_kernel<<<NN, 256>>>(gum, adjs, out_logp, t);
        // jump + ODE + intensity
        jump_kernel<<<NN, 256>>>(wd, bd, wo, event_data, t);
        ode_kernel<<<NN, 256, ODE_SMEM_BYTES>>>(wc1, bc1, wc2, bc2,
                                                wi1, bi1, wi2, bi2,
                                                event_time, t0, out, t);
    }
}